// round 5
// baseline (speedup 1.0000x reference)
#include <cuda_runtime.h>

// IF neuron: x [T=4, B=32, H=512, W=1024] fp32.
// v=0; for t: v += x[t][i]; s=(v>=1)?1:0; out[t][i]=s; v-=s;
// Pure HBM stream: 256 MB read + 256 MB write (mandatory traffic).
// R5: asymmetric cache policy — .cs loads (dead data, stay out of L2) +
// default .wb stores (accumulate dirty lines in L2, drain in long write
// bursts -> fewer DRAM read/write turnarounds).

#define T_STEPS 4
#define SPATIAL (32 * 512 * 1024)          // 16,777,216 floats per plane
#define PLANE4  (SPATIAL / 4)              // 4,194,304 float4 per plane
#define THREADS 256
#define BLOCKS  (PLANE4 / THREADS)         // 16384, exact

__global__ __launch_bounds__(THREADS) void if_neuron_kernel(
    const float4* __restrict__ x, float4* __restrict__ out)
{
    const size_t i = blockIdx.x * (size_t)THREADS + threadIdx.x;

    // Streaming loads: read-once data, evict-first so it never displaces
    // dirty output lines waiting to drain from L2.
    float4 x0 = __ldcs(x + 0 * (size_t)PLANE4 + i);
    float4 x1 = __ldcs(x + 1 * (size_t)PLANE4 + i);
    float4 x2 = __ldcs(x + 2 * (size_t)PLANE4 + i);
    float4 x3 = __ldcs(x + 3 * (size_t)PLANE4 + i);

    float v0 = 0.f, v1 = 0.f, v2 = 0.f, v3 = 0.f;
    float4 s0, s1, s2, s3;

    v0 += x0.x; v1 += x0.y; v2 += x0.z; v3 += x0.w;
    s0.x = (v0 >= 1.0f) ? 1.0f : 0.0f;
    s0.y = (v1 >= 1.0f) ? 1.0f : 0.0f;
    s0.z = (v2 >= 1.0f) ? 1.0f : 0.0f;
    s0.w = (v3 >= 1.0f) ? 1.0f : 0.0f;
    v0 -= s0.x; v1 -= s0.y; v2 -= s0.z; v3 -= s0.w;

    v0 += x1.x; v1 += x1.y; v2 += x1.z; v3 += x1.w;
    s1.x = (v0 >= 1.0f) ? 1.0f : 0.0f;
    s1.y = (v1 >= 1.0f) ? 1.0f : 0.0f;
    s1.z = (v2 >= 1.0f) ? 1.0f : 0.0f;
    s1.w = (v3 >= 1.0f) ? 1.0f : 0.0f;
    v0 -= s1.x; v1 -= s1.y; v2 -= s1.z; v3 -= s1.w;

    v0 += x2.x; v1 += x2.y; v2 += x2.z; v3 += x2.w;
    s2.x = (v0 >= 1.0f) ? 1.0f : 0.0f;
    s2.y = (v1 >= 1.0f) ? 1.0f : 0.0f;
    s2.z = (v2 >= 1.0f) ? 1.0f : 0.0f;
    s2.w = (v3 >= 1.0f) ? 1.0f : 0.0f;
    v0 -= s2.x; v1 -= s2.y; v2 -= s2.z; v3 -= s2.w;

    v0 += x3.x; v1 += x3.y; v2 += x3.z; v3 += x3.w;
    s3.x = (v0 >= 1.0f) ? 1.0f : 0.0f;
    s3.y = (v1 >= 1.0f) ? 1.0f : 0.0f;
    s3.z = (v2 >= 1.0f) ? 1.0f : 0.0f;
    s3.w = (v3 >= 1.0f) ? 1.0f : 0.0f;

    // Default write-back stores: let L2 batch the write drain.
    out[0 * (size_t)PLANE4 + i] = s0;
    out[1 * (size_t)PLANE4 + i] = s1;
    out[2 * (size_t)PLANE4 + i] = s2;
    out[3 * (size_t)PLANE4 + i] = s3;
}

extern "C" void kernel_launch(void* const* d_in, const int* in_sizes, int n_in,
                              void* d_out, int out_size)
{
    const float4* x = (const float4*)d_in[0];
    float4* out = (float4*)d_out;
    if_neuron_kernel<<<BLOCKS, THREADS>>>(x, out);
}

// round 6
// speedup vs baseline: 1.0244x; 1.0244x over previous
#include <cuda_runtime.h>

// IF neuron: x [T=4, B=32, H=512, W=1024] fp32.
// v=0; for t: v += x[t][i]; s=(v>=1)?1:0; out[t][i]=s; v-=s;
// Pure HBM stream: 256 MB read + 256 MB write (mandatory traffic).
// R6: Blackwell 256-bit global accesses (ld.global.nc.v8.f32 /
// st.global.v8.f32). Each thread owns 8 consecutive floats per plane;
// a warp touches 1024 contiguous bytes per plane per access. Halves LSU
// transactions — last untested mechanism after cache-policy / burst /
// occupancy sweeps all landed at the same ~6.25 TB/s mixed-stream ceiling.

#define T_STEPS 4
#define SPATIAL (32 * 512 * 1024)          // 16,777,216 floats per plane
#define PLANE8  (SPATIAL / 8)              // 2,097,152 float8 per plane
#define THREADS 256
#define BLOCKS  (PLANE8 / THREADS)         // 8192, exact

struct __align__(32) f8 { float v[8]; };

__device__ __forceinline__ f8 ldg256(const float* p) {
    f8 r;
    asm volatile(
        "ld.global.nc.v8.f32 {%0,%1,%2,%3,%4,%5,%6,%7}, [%8];"
        : "=f"(r.v[0]), "=f"(r.v[1]), "=f"(r.v[2]), "=f"(r.v[3]),
          "=f"(r.v[4]), "=f"(r.v[5]), "=f"(r.v[6]), "=f"(r.v[7])
        : "l"(p));
    return r;
}

__device__ __forceinline__ void stg256(float* p, const f8& r) {
    asm volatile(
        "st.global.v8.f32 [%0], {%1,%2,%3,%4,%5,%6,%7,%8};"
        :: "l"(p),
           "f"(r.v[0]), "f"(r.v[1]), "f"(r.v[2]), "f"(r.v[3]),
           "f"(r.v[4]), "f"(r.v[5]), "f"(r.v[6]), "f"(r.v[7])
        : "memory");
}

__global__ __launch_bounds__(THREADS) void if_neuron_kernel(
    const float* __restrict__ x, float* __restrict__ out)
{
    const size_t i8 = blockIdx.x * (size_t)THREADS + threadIdx.x; // float8 idx
    const size_t off = i8 * 8;

    // Front-batched 256-bit loads, one per timestep plane.
    f8 x0 = ldg256(x + 0 * (size_t)SPATIAL + off);
    f8 x1 = ldg256(x + 1 * (size_t)SPATIAL + off);
    f8 x2 = ldg256(x + 2 * (size_t)SPATIAL + off);
    f8 x3 = ldg256(x + 3 * (size_t)SPATIAL + off);

    f8 s0, s1, s2, s3;
#pragma unroll
    for (int k = 0; k < 8; ++k) {
        float v = 0.f, s;
        v += x0.v[k]; s = (v >= 1.0f) ? 1.0f : 0.0f; s0.v[k] = s; v -= s;
        v += x1.v[k]; s = (v >= 1.0f) ? 1.0f : 0.0f; s1.v[k] = s; v -= s;
        v += x2.v[k]; s = (v >= 1.0f) ? 1.0f : 0.0f; s2.v[k] = s; v -= s;
        v += x3.v[k]; s = (v >= 1.0f) ? 1.0f : 0.0f; s3.v[k] = s;
    }

    // Back-batched 256-bit stores.
    stg256(out + 0 * (size_t)SPATIAL + off, s0);
    stg256(out + 1 * (size_t)SPATIAL + off, s1);
    stg256(out + 2 * (size_t)SPATIAL + off, s2);
    stg256(out + 3 * (size_t)SPATIAL + off, s3);
}

extern "C" void kernel_launch(void* const* d_in, const int* in_sizes, int n_in,
                              void* d_out, int out_size)
{
    const float* x = (const float*)d_in[0];
    float* out = (float*)d_out;
    if_neuron_kernel<<<BLOCKS, THREADS>>>(x, out);
}